// round 13
// baseline (speedup 1.0000x reference)
#include <cuda_runtime.h>
#include <cuda_bf16.h>
#include <math.h>
#include <stdint.h>

#define BB   8
#define TT   100
#define MTOT 800
#define HH   1024
#define LL   512
#define VV   32000
#define V4   (VV / 4)

// bf16 GEMM: 128x256 CTA tile, 512 threads, 16 warps (4m x 4n), warp 32x64,
// BK=64, 2-stage cp.async, 2 CTAs/SM => 8 warps/SMSP.
#define BM 128
#define BN 256
#define BK 64
#define NCH (HH / BK)      // 16
#define GT 512
#define STAGES 2

#define ROWB 144                            // 64 bf16 (128B) + 16B pad
#define A_BYTES (BM * ROWB)                 // 18432
#define B_BYTES (BN * ROWB)                 // 36864
#define STAGE_BYTES (A_BYTES + B_BYTES)     // 55296
#define SM_BIAS 0
#define SM_ST0  1024
#define SM_TOTAL (SM_ST0 + STAGES * STAGE_BYTES)   // 111616 (x2 CTAs = 223232)

// Scratch (no cudaMalloc allowed)
__device__ float g_logits[(size_t)MTOT * VV];          // 102.4 MB
__device__ __nv_bfloat16 g_xb[(size_t)MTOT * HH];      // 1.6 MB
__device__ __nv_bfloat16 g_wt[(size_t)VV * HH];        // 65.5 MB (W^T bf16)
__device__ float g_pgen[MTOT];
__device__ float g_rsum[MTOT];
__device__ float g_C[MTOT];

// ---------------------------------------------------------------------------
__device__ __forceinline__ void cp_async16(uint32_t saddr, const void* gsrc) {
    asm volatile("cp.async.cg.shared.global [%0], [%1], 16;\n" ::"r"(saddr), "l"(gsrc));
}
__device__ __forceinline__ void cp_commit() { asm volatile("cp.async.commit_group;\n"); }
template <int N>
__device__ __forceinline__ void cp_wait() {
    asm volatile("cp.async.wait_group %0;\n" ::"n"(N));
}
__device__ __forceinline__ void ldsm_x4(unsigned& r0, unsigned& r1, unsigned& r2,
                                        unsigned& r3, uint32_t addr) {
    asm volatile("ldmatrix.sync.aligned.m8n8.x4.shared.b16 {%0,%1,%2,%3}, [%4];"
                 : "=r"(r0), "=r"(r1), "=r"(r2), "=r"(r3) : "r"(addr));
}

// ---------------------------------------------------------------------------
// Kernel 0a: convert x -> bf16
// ---------------------------------------------------------------------------
__global__ void convx_kernel(const float* __restrict__ x) {
    int i = blockIdx.x * 256 + threadIdx.x;
    const float4* x4 = (const float4*)x;
    if (i < MTOT * HH / 4) {
        float4 v = x4[i];
        __nv_bfloat162* o = (__nv_bfloat162*)g_xb + i * 2;
        o[0] = __floats2bfloat162_rn(v.x, v.y);
        o[1] = __floats2bfloat162_rn(v.z, v.w);
    }
}

// ---------------------------------------------------------------------------
// Kernel 0b: transpose+convert W[1024][32000] f32 -> g_wt[32000][1024] bf16
// ---------------------------------------------------------------------------
__global__ void transw_kernel(const float* __restrict__ W) {
    __shared__ float tile[64][65];
    int n0 = blockIdx.x * 64;
    int k0 = blockIdx.y * 64;
    int tid = threadIdx.x;
#pragma unroll
    for (int i = 0; i < 16; i++) {
        int s = tid + i * 256;
        int r = s >> 6, c = s & 63;
        tile[r][c] = W[(size_t)(k0 + r) * VV + n0 + c];
    }
    __syncthreads();
#pragma unroll
    for (int i = 0; i < 8; i++) {
        int s = tid + i * 256;
        int nr = s >> 5, kp = s & 31;
        __nv_bfloat162 v = __floats2bfloat162_rn(tile[2 * kp][nr], tile[2 * kp + 1][nr]);
        *(__nv_bfloat162*)(g_wt + (size_t)(n0 + nr) * HH + k0 + 2 * kp) = v;
    }
}

// ---------------------------------------------------------------------------
// Kernel 1: p_gen + zero rsum
// ---------------------------------------------------------------------------
__global__ void pgen_kernel(const float* __restrict__ x,
                            const float* __restrict__ w_gen,
                            const float* __restrict__ b_gen) {
    int row = blockIdx.x;
    if (threadIdx.x == 0) g_rsum[row] = 0.f;
    const float4* xr = (const float4*)(x + (size_t)row * HH);
    const float4* wr = (const float4*)w_gen;
    float s = 0.f;
    for (int i = threadIdx.x; i < HH / 4; i += 256) {
        float4 a = xr[i], b = wr[i];
        s += a.x * b.x + a.y * b.y + a.z * b.z + a.w * b.w;
    }
    __shared__ float red[256];
    red[threadIdx.x] = s;
    __syncthreads();
    for (int off = 128; off > 0; off >>= 1) {
        if (threadIdx.x < off) red[threadIdx.x] += red[threadIdx.x + off];
        __syncthreads();
    }
    if (threadIdx.x == 0) {
        float z = red[0] + b_gen[0];
        g_pgen[row] = 1.f / (1.f + expf(-z));
    }
}

// ---------------------------------------------------------------------------
// Kernel 2: bf16 GEMM m16n8k16, 512 thr, warp 32x64, 2-stage, 2 CTAs/SM.
// ---------------------------------------------------------------------------
__global__ __launch_bounds__(GT, 2)
void gemm_bf16(const float* __restrict__ bias) {
    extern __shared__ __align__(128) char smem[];
    const uint32_t sbase = (uint32_t)__cvta_generic_to_shared(smem);

    const int tid   = threadIdx.x;
    const int lane  = tid & 31;
    const int warp  = tid >> 5;
    const int warpM = warp >> 2;      // 0..3 (32 rows)
    const int warpN = warp & 3;       // 0..3 (64 cols)
    const int g     = lane >> 2;
    const int t     = lane & 3;
    const int m0    = blockIdx.x * BM;
    const int n0    = blockIdx.y * BN;

    if (tid < BN) *(float*)(smem + SM_BIAS + tid * 4) = bias[n0 + tid];

    float acc[2][8][4];
#pragma unroll
    for (int i = 0; i < 2; i++)
#pragma unroll
        for (int j = 0; j < 8; j++)
#pragma unroll
            for (int k = 0; k < 4; k++) acc[i][j][k] = 0.f;

    const int q  = lane >> 3;
    const int rr = lane & 7;
    const uint32_t a_lane = (uint32_t)((warpM * 32 + (q & 1) * 8 + rr) * ROWB
                                       + (q >> 1) * 16);
    const uint32_t b_lane = (uint32_t)((warpN * 64 + (q >> 1) * 8 + rr) * ROWB
                                       + (q & 1) * 16);

    // per stage: A 1024 cp16 (2/thread), B 2048 cp16 (4/thread)
    auto load_stage = [&](int ch, int st) {
        const int kg = ch * BK;
        const uint32_t abuf = sbase + SM_ST0 + st * STAGE_BYTES;
        const uint32_t bbuf = abuf + A_BYTES;
#pragma unroll
        for (int i = 0; i < 2; i++) {
            int s = tid + i * 512;
            int r = s >> 3, c = s & 7;
            int gr = m0 + r;
            if (gr >= MTOT) gr = MTOT - 1;
            cp_async16(abuf + r * ROWB + c * 16, g_xb + (size_t)gr * HH + kg + c * 8);
        }
#pragma unroll
        for (int i = 0; i < 4; i++) {
            int s = tid + i * 512;
            int n = s >> 3, c = s & 7;
            cp_async16(bbuf + n * ROWB + c * 16, g_wt + (size_t)(n0 + n) * HH + kg + c * 8);
        }
        cp_commit();
    };

    load_stage(0, 0);

    for (int ch = 0; ch < NCH; ch++) {
        if (ch + 1 < NCH) {
            load_stage(ch + 1, (ch + 1) & 1);
            cp_wait<1>();
        } else {
            cp_wait<0>();
        }
        __syncthreads();

        const uint32_t abuf = sbase + SM_ST0 + (ch & 1) * STAGE_BYTES;
        const uint32_t bbuf = abuf + A_BYTES;

#pragma unroll
        for (int h = 0; h < 4; h++) {     // four k16 slices per BK=64
            unsigned a[2][4], b[8][2];
#pragma unroll
            for (int mi = 0; mi < 2; mi++)
                ldsm_x4(a[mi][0], a[mi][1], a[mi][2], a[mi][3],
                        abuf + a_lane + mi * (16 * ROWB) + h * 32);
#pragma unroll
            for (int j = 0; j < 4; j++)
                ldsm_x4(b[2 * j][0], b[2 * j][1], b[2 * j + 1][0], b[2 * j + 1][1],
                        bbuf + b_lane + j * (16 * ROWB) + h * 32);
#pragma unroll
            for (int mi = 0; mi < 2; mi++)
#pragma unroll
                for (int ni = 0; ni < 8; ni++) {
                    asm volatile(
                        "mma.sync.aligned.m16n8k16.row.col.f32.bf16.bf16.f32 "
                        "{%0,%1,%2,%3}, {%4,%5,%6,%7}, {%8,%9}, {%0,%1,%2,%3};"
                        : "+f"(acc[mi][ni][0]), "+f"(acc[mi][ni][1]),
                          "+f"(acc[mi][ni][2]), "+f"(acc[mi][ni][3])
                        : "r"(a[mi][0]), "r"(a[mi][1]), "r"(a[mi][2]), "r"(a[mi][3]),
                          "r"(b[ni][0]), "r"(b[ni][1]));
                }
        }
        __syncthreads();
    }

    // Epilogue: bias + write logits + per-row sum of exp
    const float* sb = (const float*)(smem + SM_BIAS);
    float psum_lo[2] = {0.f, 0.f};
    float psum_hi[2] = {0.f, 0.f};
#pragma unroll
    for (int ni = 0; ni < 8; ni++) {
        int cl = warpN * 64 + ni * 8 + 2 * t;
        int c  = n0 + cl;
        float b0 = sb[cl], b1 = sb[cl + 1];
#pragma unroll
        for (int mi = 0; mi < 2; mi++) {
            int r = m0 + warpM * 32 + mi * 16 + g;
            float l0 = acc[mi][ni][0] + b0, l1 = acc[mi][ni][1] + b1;
            float l2 = acc[mi][ni][2] + b0, l3 = acc[mi][ni][3] + b1;
            if (r < MTOT) {
                *reinterpret_cast<float2*>(g_logits + (size_t)r * VV + c) =
                    make_float2(l0, l1);
                psum_lo[mi] += __expf(l0) + __expf(l1);
            }
            if (r + 8 < MTOT) {
                *reinterpret_cast<float2*>(g_logits + (size_t)(r + 8) * VV + c) =
                    make_float2(l2, l3);
                psum_hi[mi] += __expf(l2) + __expf(l3);
            }
        }
    }
    __syncthreads();
    float* srow = (float*)smem;
    if (tid < BM) srow[tid] = 0.f;
    __syncthreads();
#pragma unroll
    for (int mi = 0; mi < 2; mi++) {
        atomicAdd(&srow[warpM * 32 + mi * 16 + g], psum_lo[mi]);
        atomicAdd(&srow[warpM * 32 + mi * 16 + 8 + g], psum_hi[mi]);
    }
    __syncthreads();
    if (tid < BM && m0 + tid < MTOT) atomicAdd(&g_rsum[m0 + tid], srow[tid]);
}

// ---------------------------------------------------------------------------
// Kernel 3: g_C[r] = log(p_gen / sum_exp)
// ---------------------------------------------------------------------------
__global__ void prep_kernel() {
    int r = blockIdx.x * 256 + threadIdx.x;
    if (r < MTOT) g_C[r] = logf(g_pgen[r] / g_rsum[r]);
}

// ---------------------------------------------------------------------------
// Kernel 4: dense pass — out[row, v] = logit[row, v] + C[row]
// ---------------------------------------------------------------------------
__global__ void dense_kernel(float* __restrict__ out) {
    int row = blockIdx.y;
    float C = g_C[row];
    const float4* l4 = (const float4*)(g_logits + (size_t)row * VV);
    float4* o4 = (float4*)(out + (size_t)row * VV);
    int j = blockIdx.x * 256 + threadIdx.x;
#pragma unroll
    for (int k = 0; k < 4; k++) {
        int i = j + k * 2048;
        if (i < V4) {
            float4 l = l4[i];
            l.x += C; l.y += C; l.z += C; l.w += C;
            o4[i] = l;
        }
    }
}

// ---------------------------------------------------------------------------
// Kernel 5: hash-merge copy distribution + apply at touched slots.
// ---------------------------------------------------------------------------
__global__ void hashapply_kernel(const float* __restrict__ attn,
                                 const int* __restrict__ enc,
                                 float* __restrict__ out) {
    int row = blockIdx.x;
    int b   = row / TT;
    const float* ar = attn + (size_t)row * LL;
    int tid = threadIdx.x;   // 256

    __shared__ float av[LL];
    __shared__ float red[256];
    __shared__ int   hidx[1024];
    __shared__ float hval[1024];

#pragma unroll
    for (int i = tid; i < 1024; i += 256) { hidx[i] = -1; hval[i] = 0.f; }

    float m = -1e30f;
    for (int l = tid; l < LL; l += 256) {
        float a = ar[l];
        av[l] = a;
        m = fmaxf(m, a);
    }
    red[tid] = m;
    __syncthreads();
    for (int off = 128; off > 0; off >>= 1) {
        if (tid < off) red[tid] = fmaxf(red[tid], red[tid + off]);
        __syncthreads();
    }
    m = red[0];
    __syncthreads();

    float s = 0.f;
    for (int l = tid; l < LL; l += 256) s += __expf(av[l] - m);
    red[tid] = s;
    __syncthreads();
    for (int off = 128; off > 0; off >>= 1) {
        if (tid < off) red[tid] += red[tid + off];
        __syncthreads();
    }
    s = red[0];

    float scale = (1.f - g_pgen[row]) / s;
    for (int l = tid; l < LL; l += 256) {
        float v = scale * __expf(av[l] - m);
        int id = enc[b * LL + l];
        int h = id & 1023;
        while (true) {
            int prev = atomicCAS(&hidx[h], -1, id);
            if (prev == -1 || prev == id) { atomicAdd(&hval[h], v); break; }
            h = (h + 1) & 1023;
        }
    }
    __syncthreads();

    for (int sslot = tid; sslot < 1024; sslot += 256) {
        int id = hidx[sslot];
        if (id >= 0) {
            size_t o = (size_t)row * VV + id;
            out[o] = __logf(hval[sslot] + __expf(out[o]));
        }
    }
}

// ---------------------------------------------------------------------------
extern "C" void kernel_launch(void* const* d_in, const int* in_sizes, int n_in,
                              void* d_out, int out_size) {
    const float* x    = (const float*)d_in[0];
    const float* attn = (const float*)d_in[1];
    const int*   enc  = (const int*)  d_in[2];
    const float* Wv   = (const float*)d_in[3];
    const float* bv   = (const float*)d_in[4];
    const float* wg   = (const float*)d_in[5];
    const float* bg   = (const float*)d_in[6];
    float* out = (float*)d_out;

    static bool attr_set = false;
    if (!attr_set) {
        cudaFuncSetAttribute(gemm_bf16, cudaFuncAttributeMaxDynamicSharedMemorySize,
                             SM_TOTAL);
        attr_set = true;
    }

    convx_kernel<<<(MTOT * HH / 4 + 255) / 256, 256>>>(x);
    dim3 tgrid(VV / 64, HH / 64);
    transw_kernel<<<tgrid, 256>>>(Wv);
    pgen_kernel<<<MTOT, 256>>>(x, wg, bg);

    dim3 ggrid((MTOT + BM - 1) / BM, VV / BN);   // (7, 125), m fastest
    gemm_bf16<<<ggrid, GT, SM_TOTAL>>>(bv);

    prep_kernel<<<4, 256>>>();

    dim3 dgrid(8, MTOT);
    dense_kernel<<<dgrid, 256>>>(out);

    hashapply_kernel<<<MTOT, 256>>>(attn, enc, out);
}

// round 14
// speedup vs baseline: 2.3480x; 2.3480x over previous
#include <cuda_runtime.h>
#include <cuda_bf16.h>
#include <math.h>
#include <stdint.h>

#define BB   8
#define TT   100
#define MTOT 800
#define HH   1024
#define LL   512
#define VV   32000
#define V4   (VV / 4)

// bf16 GEMM: 128x128 CTA tile, 256 threads, 8 warps (2m x 4n), warp 64x32,
// BK=64, 3-stage cp.async, one __syncthreads per chunk, 2 CTAs/SM. (R11 best)
#define BM 128
#define BN 128
#define BK 64
#define NCH (HH / BK)      // 16
#define GT 256
#define STAGES 3

#define ROWB 144                            // 64 bf16 (128B) + 16B pad
#define A_BYTES (BM * ROWB)                 // 18432
#define B_BYTES (BN * ROWB)                 // 18432
#define STAGE_BYTES (A_BYTES + B_BYTES)     // 36864
#define SM_BIAS 0
#define SM_ST0  1024
#define SM_TOTAL (SM_ST0 + STAGES * STAGE_BYTES)   // 111616 (x2 CTAs = 223232)

// Scratch (no cudaMalloc allowed)
__device__ float g_logits[(size_t)MTOT * VV];          // 102.4 MB
__device__ __nv_bfloat16 g_xb[(size_t)MTOT * HH];      // 1.6 MB
__device__ __nv_bfloat16 g_wt[(size_t)VV * HH];        // 65.5 MB (W^T bf16)
__device__ float g_pgen[MTOT];
__device__ float g_rsum[MTOT];

// ---------------------------------------------------------------------------
__device__ __forceinline__ void cp_async16(uint32_t saddr, const void* gsrc) {
    asm volatile("cp.async.cg.shared.global [%0], [%1], 16;\n" ::"r"(saddr), "l"(gsrc));
}
__device__ __forceinline__ void cp_commit() { asm volatile("cp.async.commit_group;\n"); }
template <int N>
__device__ __forceinline__ void cp_wait() {
    asm volatile("cp.async.wait_group %0;\n" ::"n"(N));
}
__device__ __forceinline__ void ldsm_x4(unsigned& r0, unsigned& r1, unsigned& r2,
                                        unsigned& r3, uint32_t addr) {
    asm volatile("ldmatrix.sync.aligned.m8n8.x4.shared.b16 {%0,%1,%2,%3}, [%4];"
                 : "=r"(r0), "=r"(r1), "=r"(r2), "=r"(r3) : "r"(addr));
}

// ---------------------------------------------------------------------------
// Kernel 0: transpose+convert W[1024][32000] f32 -> g_wt[32000][1024] bf16
// ---------------------------------------------------------------------------
__global__ void transw_kernel(const float* __restrict__ W) {
    __shared__ float tile[64][65];
    int n0 = blockIdx.x * 64;
    int k0 = blockIdx.y * 64;
    int tid = threadIdx.x;
#pragma unroll
    for (int i = 0; i < 16; i++) {
        int s = tid + i * 256;
        int r = s >> 6, c = s & 63;
        tile[r][c] = W[(size_t)(k0 + r) * VV + n0 + c];
    }
    __syncthreads();
#pragma unroll
    for (int i = 0; i < 8; i++) {
        int s = tid + i * 256;
        int nr = s >> 5, kp = s & 31;
        __nv_bfloat162 v = __floats2bfloat162_rn(tile[2 * kp][nr], tile[2 * kp + 1][nr]);
        *(__nv_bfloat162*)(g_wt + (size_t)(n0 + nr) * HH + k0 + 2 * kp) = v;
    }
}

// ---------------------------------------------------------------------------
// Kernel 1: fused x->bf16 convert + p_gen + zero rsum.
// One block per row, 256 threads, each handles exactly one float4 of the row.
// ---------------------------------------------------------------------------
__global__ void pgen_kernel(const float* __restrict__ x,
                            const float* __restrict__ w_gen,
                            const float* __restrict__ b_gen) {
    int row = blockIdx.x;
    int i   = threadIdx.x;            // 0..255 == HH/4 slots
    if (i == 0) g_rsum[row] = 0.f;
    float4 a = ((const float4*)(x + (size_t)row * HH))[i];
    float4 b = ((const float4*)w_gen)[i];
    // convert to bf16 scratch
    __nv_bfloat162* o = (__nv_bfloat162*)(g_xb + (size_t)row * HH) + i * 2;
    o[0] = __floats2bfloat162_rn(a.x, a.y);
    o[1] = __floats2bfloat162_rn(a.z, a.w);
    // dot product partial
    float s = a.x * b.x + a.y * b.y + a.z * b.z + a.w * b.w;
    __shared__ float red[256];
    red[i] = s;
    __syncthreads();
    for (int off = 128; off > 0; off >>= 1) {
        if (i < off) red[i] += red[i + off];
        __syncthreads();
    }
    if (i == 0) {
        float z = red[0] + b_gen[0];
        g_pgen[row] = 1.f / (1.f + expf(-z));
    }
}

// ---------------------------------------------------------------------------
// Kernel 2: bf16 GEMM m16n8k16, BK=64, 3-stage, 1 sync/chunk, 2 CTAs/SM.
// ---------------------------------------------------------------------------
__global__ __launch_bounds__(GT, 2)
void gemm_bf16(const float* __restrict__ bias) {
    extern __shared__ __align__(128) char smem[];
    const uint32_t sbase = (uint32_t)__cvta_generic_to_shared(smem);

    const int tid   = threadIdx.x;
    const int lane  = tid & 31;
    const int warp  = tid >> 5;
    const int warpM = warp & 1;       // 64 rows
    const int warpN = warp >> 1;      // 32 cols
    const int g     = lane >> 2;
    const int t     = lane & 3;
    const int m0    = blockIdx.x * BM;
    const int n0    = blockIdx.y * BN;

    if (tid < BN) *(float*)(smem + SM_BIAS + tid * 4) = bias[n0 + tid];

    float acc[4][4][4];
#pragma unroll
    for (int i = 0; i < 4; i++)
#pragma unroll
        for (int j = 0; j < 4; j++)
#pragma unroll
            for (int k = 0; k < 4; k++) acc[i][j][k] = 0.f;

    const int q  = lane >> 3;
    const int rr = lane & 7;
    const uint32_t a_lane = (uint32_t)((warpM * 64 + (q & 1) * 8 + rr) * ROWB
                                       + (q >> 1) * 16);
    const uint32_t b_lane = (uint32_t)((warpN * 32 + (q >> 1) * 8 + rr) * ROWB
                                       + (q & 1) * 16);

    auto load_stage = [&](int ch, int st) {
        const int kg = ch * BK;
        const uint32_t abuf = sbase + SM_ST0 + st * STAGE_BYTES;
        const uint32_t bbuf = abuf + A_BYTES;
#pragma unroll
        for (int i = 0; i < 4; i++) {
            int s = tid + i * 256;
            int r = s >> 3, c = s & 7;
            int gr = m0 + r;
            if (gr >= MTOT) gr = MTOT - 1;
            cp_async16(abuf + r * ROWB + c * 16, g_xb + (size_t)gr * HH + kg + c * 8);
        }
#pragma unroll
        for (int i = 0; i < 4; i++) {
            int s = tid + i * 256;
            int n = s >> 3, c = s & 7;
            cp_async16(bbuf + n * ROWB + c * 16, g_wt + (size_t)(n0 + n) * HH + kg + c * 8);
        }
        cp_commit();
    };

    load_stage(0, 0);
    load_stage(1, 1);

    for (int ch = 0; ch < NCH; ch++) {
        if (ch + 1 < NCH) cp_wait<1>();
        else cp_wait<0>();
        __syncthreads();   // one barrier per chunk; 3-stage rotation keeps WAR safe

        if (ch + 2 < NCH) load_stage(ch + 2, (ch + 2) % STAGES);

        const uint32_t abuf = sbase + SM_ST0 + (ch % STAGES) * STAGE_BYTES;
        const uint32_t bbuf = abuf + A_BYTES;

#pragma unroll
        for (int h = 0; h < 4; h++) {
            unsigned a[4][4], b[4][2];
#pragma unroll
            for (int mi = 0; mi < 4; mi++)
                ldsm_x4(a[mi][0], a[mi][1], a[mi][2], a[mi][3],
                        abuf + a_lane + mi * (16 * ROWB) + h * 32);
#pragma unroll
            for (int j = 0; j < 2; j++)
                ldsm_x4(b[2 * j][0], b[2 * j][1], b[2 * j + 1][0], b[2 * j + 1][1],
                        bbuf + b_lane + j * (16 * ROWB) + h * 32);
#pragma unroll
            for (int mi = 0; mi < 4; mi++)
#pragma unroll
                for (int ni = 0; ni < 4; ni++) {
                    asm volatile(
                        "mma.sync.aligned.m16n8k16.row.col.f32.bf16.bf16.f32 "
                        "{%0,%1,%2,%3}, {%4,%5,%6,%7}, {%8,%9}, {%0,%1,%2,%3};"
                        : "+f"(acc[mi][ni][0]), "+f"(acc[mi][ni][1]),
                          "+f"(acc[mi][ni][2]), "+f"(acc[mi][ni][3])
                        : "r"(a[mi][0]), "r"(a[mi][1]), "r"(a[mi][2]), "r"(a[mi][3]),
                          "r"(b[ni][0]), "r"(b[ni][1]));
                }
        }
    }
    __syncthreads();

    // Epilogue: bias + write logits + per-row sum of exp
    const float* sb = (const float*)(smem + SM_BIAS);
    float psum_lo[4] = {0.f, 0.f, 0.f, 0.f};
    float psum_hi[4] = {0.f, 0.f, 0.f, 0.f};
#pragma unroll
    for (int ni = 0; ni < 4; ni++) {
        int cl = warpN * 32 + ni * 8 + 2 * t;
        int c  = n0 + cl;
        float b0 = sb[cl], b1 = sb[cl + 1];
#pragma unroll
        for (int mi = 0; mi < 4; mi++) {
            int r = m0 + warpM * 64 + mi * 16 + g;
            float l0 = acc[mi][ni][0] + b0, l1 = acc[mi][ni][1] + b1;
            float l2 = acc[mi][ni][2] + b0, l3 = acc[mi][ni][3] + b1;
            if (r < MTOT) {
                *reinterpret_cast<float2*>(g_logits + (size_t)r * VV + c) =
                    make_float2(l0, l1);
                psum_lo[mi] += __expf(l0) + __expf(l1);
            }
            if (r + 8 < MTOT) {
                *reinterpret_cast<float2*>(g_logits + (size_t)(r + 8) * VV + c) =
                    make_float2(l2, l3);
                psum_hi[mi] += __expf(l2) + __expf(l3);
            }
        }
    }
    __syncthreads();
    float* srow = (float*)smem;
    if (tid < BM) srow[tid] = 0.f;
    __syncthreads();
#pragma unroll
    for (int mi = 0; mi < 4; mi++) {
        atomicAdd(&srow[warpM * 64 + mi * 16 + g], psum_lo[mi]);
        atomicAdd(&srow[warpM * 64 + mi * 16 + 8 + g], psum_hi[mi]);
    }
    __syncthreads();
    if (tid < BM && m0 + tid < MTOT) atomicAdd(&g_rsum[m0 + tid], srow[tid]);
}

// ---------------------------------------------------------------------------
// Kernel 3: dense pass — out[row, v] = logit[row, v] + log(pgen/rsum)
//   (prep fused: C computed per block from g_pgen/g_rsum)
// ---------------------------------------------------------------------------
__global__ void dense_kernel(float* __restrict__ out) {
    int row = blockIdx.y;
    float C = __logf(g_pgen[row] / g_rsum[row]);
    const float4* l4 = (const float4*)(g_logits + (size_t)row * VV);
    float4* o4 = (float4*)(out + (size_t)row * VV);
    int j = blockIdx.x * 256 + threadIdx.x;
#pragma unroll
    for (int k = 0; k < 4; k++) {
        int i = j + k * 2048;
        if (i < V4) {
            float4 l = l4[i];
            l.x += C; l.y += C; l.z += C; l.w += C;
            o4[i] = l;
        }
    }
}

// ---------------------------------------------------------------------------
// Kernel 4: hash-merge copy distribution + apply at touched slots.
// ---------------------------------------------------------------------------
__global__ void hashapply_kernel(const float* __restrict__ attn,
                                 const int* __restrict__ enc,
                                 float* __restrict__ out) {
    int row = blockIdx.x;
    int b   = row / TT;
    const float* ar = attn + (size_t)row * LL;
    int tid = threadIdx.x;   // 256

    __shared__ float av[LL];
    __shared__ float red[256];
    __shared__ int   hidx[1024];
    __shared__ float hval[1024];

#pragma unroll
    for (int i = tid; i < 1024; i += 256) { hidx[i] = -1; hval[i] = 0.f; }

    float m = -1e30f;
    for (int l = tid; l < LL; l += 256) {
        float a = ar[l];
        av[l] = a;
        m = fmaxf(m, a);
    }
    red[tid] = m;
    __syncthreads();
    for (int off = 128; off > 0; off >>= 1) {
        if (tid < off) red[tid] = fmaxf(red[tid], red[tid + off]);
        __syncthreads();
    }
    m = red[0];
    __syncthreads();

    float s = 0.f;
    for (int l = tid; l < LL; l += 256) s += __expf(av[l] - m);
    red[tid] = s;
    __syncthreads();
    for (int off = 128; off > 0; off >>= 1) {
        if (tid < off) red[tid] += red[tid + off];
        __syncthreads();
    }
    s = red[0];

    float scale = (1.f - g_pgen[row]) / s;
    for (int l = tid; l < LL; l += 256) {
        float v = scale * __expf(av[l] - m);
        int id = enc[b * LL + l];
        int h = id & 1023;
        while (true) {
            int prev = atomicCAS(&hidx[h], -1, id);
            if (prev == -1 || prev == id) { atomicAdd(&hval[h], v); break; }
            h = (h + 1) & 1023;
        }
    }
    __syncthreads();

    for (int sslot = tid; sslot < 1024; sslot += 256) {
        int id = hidx[sslot];
        if (id >= 0) {
            size_t o = (size_t)row * VV + id;
            out[o] = __logf(hval[sslot] + __expf(out[o]));
        }
    }
}

// ---------------------------------------------------------------------------
extern "C" void kernel_launch(void* const* d_in, const int* in_sizes, int n_in,
                              void* d_out, int out_size) {
    const float* x    = (const float*)d_in[0];
    const float* attn = (const float*)d_in[1];
    const int*   enc  = (const int*)  d_in[2];
    const float* Wv   = (const float*)d_in[3];
    const float* bv   = (const float*)d_in[4];
    const float* wg   = (const float*)d_in[5];
    const float* bg   = (const float*)d_in[6];
    float* out = (float*)d_out;

    static bool attr_set = false;
    if (!attr_set) {
        cudaFuncSetAttribute(gemm_bf16, cudaFuncAttributeMaxDynamicSharedMemorySize,
                             SM_TOTAL);
        attr_set = true;
    }

    dim3 tgrid(VV / 64, HH / 64);
    transw_kernel<<<tgrid, 256>>>(Wv);
    pgen_kernel<<<MTOT, 256>>>(x, wg, bg);

    dim3 ggrid((MTOT + BM - 1) / BM, VV / BN);   // (7, 250), m fastest
    gemm_bf16<<<ggrid, GT, SM_TOTAL>>>(bv);

    dim3 dgrid(8, MTOT);
    dense_kernel<<<dgrid, 256>>>(out);

    hashapply_kernel<<<MTOT, 256>>>(attn, enc, out);
}

// round 15
// speedup vs baseline: 2.3796x; 1.0135x over previous
#include <cuda_runtime.h>
#include <cuda_bf16.h>
#include <math.h>
#include <stdint.h>

#define BB   8
#define TT   100
#define MTOT 800
#define HH   1024
#define LL   512
#define VV   32000
#define V4   (VV / 4)

// bf16 GEMM: 128x128 CTA tile, 256 threads, 8 warps (2m x 4n), warp 64x32,
// BK=64, 3-stage cp.async, one __syncthreads per chunk, 2 CTAs/SM.
#define BM 128
#define BN 128
#define BK 64
#define NCH (HH / BK)      // 16
#define GT 256
#define STAGES 3

#define ROWB 144                            // 64 bf16 (128B) + 16B pad
#define A_BYTES (BM * ROWB)                 // 18432
#define B_BYTES (BN * ROWB)                 // 18432
#define STAGE_BYTES (A_BYTES + B_BYTES)     // 36864
#define SM_BIAS 0
#define SM_ST0  1024
#define SM_TOTAL (SM_ST0 + STAGES * STAGE_BYTES)   // 111616 (x2 CTAs = 223232)

// Scratch (no cudaMalloc allowed) — logits now live in d_out directly.
__device__ __nv_bfloat16 g_xb[(size_t)MTOT * HH];      // 1.6 MB
__device__ __nv_bfloat16 g_wt[(size_t)VV * HH];        // 65.5 MB (W^T bf16)
__device__ float g_pgen[MTOT];
__device__ float g_rsum[MTOT];

// ---------------------------------------------------------------------------
__device__ __forceinline__ void cp_async16(uint32_t saddr, const void* gsrc) {
    asm volatile("cp.async.cg.shared.global [%0], [%1], 16;\n" ::"r"(saddr), "l"(gsrc));
}
__device__ __forceinline__ void cp_commit() { asm volatile("cp.async.commit_group;\n"); }
template <int N>
__device__ __forceinline__ void cp_wait() {
    asm volatile("cp.async.wait_group %0;\n" ::"n"(N));
}
__device__ __forceinline__ void ldsm_x4(unsigned& r0, unsigned& r1, unsigned& r2,
                                        unsigned& r3, uint32_t addr) {
    asm volatile("ldmatrix.sync.aligned.m8n8.x4.shared.b16 {%0,%1,%2,%3}, [%4];"
                 : "=r"(r0), "=r"(r1), "=r"(r2), "=r"(r3) : "r"(addr));
}

// ---------------------------------------------------------------------------
// Kernel 0: transpose+convert W[1024][32000] f32 -> g_wt[32000][1024] bf16
// ---------------------------------------------------------------------------
__global__ void transw_kernel(const float* __restrict__ W) {
    __shared__ float tile[64][65];
    int n0 = blockIdx.x * 64;
    int k0 = blockIdx.y * 64;
    int tid = threadIdx.x;
#pragma unroll
    for (int i = 0; i < 16; i++) {
        int s = tid + i * 256;
        int r = s >> 6, c = s & 63;
        tile[r][c] = W[(size_t)(k0 + r) * VV + n0 + c];
    }
    __syncthreads();
#pragma unroll
    for (int i = 0; i < 8; i++) {
        int s = tid + i * 256;
        int nr = s >> 5, kp = s & 31;
        __nv_bfloat162 v = __floats2bfloat162_rn(tile[2 * kp][nr], tile[2 * kp + 1][nr]);
        *(__nv_bfloat162*)(g_wt + (size_t)(n0 + nr) * HH + k0 + 2 * kp) = v;
    }
}

// ---------------------------------------------------------------------------
// Kernel 1: fused x->bf16 convert + p_gen + zero rsum.
// ---------------------------------------------------------------------------
__global__ void pgen_kernel(const float* __restrict__ x,
                            const float* __restrict__ w_gen,
                            const float* __restrict__ b_gen) {
    int row = blockIdx.x;
    int i   = threadIdx.x;            // 0..255 == HH/4 slots
    if (i == 0) g_rsum[row] = 0.f;
    float4 a = ((const float4*)(x + (size_t)row * HH))[i];
    float4 b = ((const float4*)w_gen)[i];
    __nv_bfloat162* o = (__nv_bfloat162*)(g_xb + (size_t)row * HH) + i * 2;
    o[0] = __floats2bfloat162_rn(a.x, a.y);
    o[1] = __floats2bfloat162_rn(a.z, a.w);
    float s = a.x * b.x + a.y * b.y + a.z * b.z + a.w * b.w;
    __shared__ float red[256];
    red[i] = s;
    __syncthreads();
    for (int off = 128; off > 0; off >>= 1) {
        if (i < off) red[i] += red[i + off];
        __syncthreads();
    }
    if (i == 0) {
        float z = red[0] + b_gen[0];
        g_pgen[row] = 1.f / (1.f + expf(-z));
    }
}

// ---------------------------------------------------------------------------
// Kernel 2: bf16 GEMM m16n8k16, BK=64, 3-stage, 1 sync/chunk, 2 CTAs/SM.
// Writes bias-added logits DIRECTLY into out; accumulates per-row sum(exp).
// ---------------------------------------------------------------------------
__global__ __launch_bounds__(GT, 2)
void gemm_bf16(const float* __restrict__ bias, float* __restrict__ out) {
    extern __shared__ __align__(128) char smem[];
    const uint32_t sbase = (uint32_t)__cvta_generic_to_shared(smem);

    const int tid   = threadIdx.x;
    const int lane  = tid & 31;
    const int warp  = tid >> 5;
    const int warpM = warp & 1;       // 64 rows
    const int warpN = warp >> 1;      // 32 cols
    const int g     = lane >> 2;
    const int t     = lane & 3;
    const int m0    = blockIdx.x * BM;
    const int n0    = blockIdx.y * BN;

    if (tid < BN) *(float*)(smem + SM_BIAS + tid * 4) = bias[n0 + tid];

    float acc[4][4][4];
#pragma unroll
    for (int i = 0; i < 4; i++)
#pragma unroll
        for (int j = 0; j < 4; j++)
#pragma unroll
            for (int k = 0; k < 4; k++) acc[i][j][k] = 0.f;

    const int q  = lane >> 3;
    const int rr = lane & 7;
    const uint32_t a_lane = (uint32_t)((warpM * 64 + (q & 1) * 8 + rr) * ROWB
                                       + (q >> 1) * 16);
    const uint32_t b_lane = (uint32_t)((warpN * 32 + (q >> 1) * 8 + rr) * ROWB
                                       + (q & 1) * 16);

    auto load_stage = [&](int ch, int st) {
        const int kg = ch * BK;
        const uint32_t abuf = sbase + SM_ST0 + st * STAGE_BYTES;
        const uint32_t bbuf = abuf + A_BYTES;
#pragma unroll
        for (int i = 0; i < 4; i++) {
            int s = tid + i * 256;
            int r = s >> 3, c = s & 7;
            int gr = m0 + r;
            if (gr >= MTOT) gr = MTOT - 1;
            cp_async16(abuf + r * ROWB + c * 16, g_xb + (size_t)gr * HH + kg + c * 8);
        }
#pragma unroll
        for (int i = 0; i < 4; i++) {
            int s = tid + i * 256;
            int n = s >> 3, c = s & 7;
            cp_async16(bbuf + n * ROWB + c * 16, g_wt + (size_t)(n0 + n) * HH + kg + c * 8);
        }
        cp_commit();
    };

    load_stage(0, 0);
    load_stage(1, 1);

    for (int ch = 0; ch < NCH; ch++) {
        if (ch + 1 < NCH) cp_wait<1>();
        else cp_wait<0>();
        __syncthreads();   // one barrier per chunk; 3-stage rotation keeps WAR safe

        if (ch + 2 < NCH) load_stage(ch + 2, (ch + 2) % STAGES);

        const uint32_t abuf = sbase + SM_ST0 + (ch % STAGES) * STAGE_BYTES;
        const uint32_t bbuf = abuf + A_BYTES;

#pragma unroll
        for (int h = 0; h < 4; h++) {
            unsigned a[4][4], b[4][2];
#pragma unroll
            for (int mi = 0; mi < 4; mi++)
                ldsm_x4(a[mi][0], a[mi][1], a[mi][2], a[mi][3],
                        abuf + a_lane + mi * (16 * ROWB) + h * 32);
#pragma unroll
            for (int j = 0; j < 2; j++)
                ldsm_x4(b[2 * j][0], b[2 * j][1], b[2 * j + 1][0], b[2 * j + 1][1],
                        bbuf + b_lane + j * (16 * ROWB) + h * 32);
#pragma unroll
            for (int mi = 0; mi < 4; mi++)
#pragma unroll
                for (int ni = 0; ni < 4; ni++) {
                    asm volatile(
                        "mma.sync.aligned.m16n8k16.row.col.f32.bf16.bf16.f32 "
                        "{%0,%1,%2,%3}, {%4,%5,%6,%7}, {%8,%9}, {%0,%1,%2,%3};"
                        : "+f"(acc[mi][ni][0]), "+f"(acc[mi][ni][1]),
                          "+f"(acc[mi][ni][2]), "+f"(acc[mi][ni][3])
                        : "r"(a[mi][0]), "r"(a[mi][1]), "r"(a[mi][2]), "r"(a[mi][3]),
                          "r"(b[ni][0]), "r"(b[ni][1]));
                }
        }
    }
    __syncthreads();

    // Epilogue: bias + write logits into out + per-row sum of exp
    const float* sb = (const float*)(smem + SM_BIAS);
    float psum_lo[4] = {0.f, 0.f, 0.f, 0.f};
    float psum_hi[4] = {0.f, 0.f, 0.f, 0.f};
#pragma unroll
    for (int ni = 0; ni < 4; ni++) {
        int cl = warpN * 32 + ni * 8 + 2 * t;
        int c  = n0 + cl;
        float b0 = sb[cl], b1 = sb[cl + 1];
#pragma unroll
        for (int mi = 0; mi < 4; mi++) {
            int r = m0 + warpM * 64 + mi * 16 + g;
            float l0 = acc[mi][ni][0] + b0, l1 = acc[mi][ni][1] + b1;
            float l2 = acc[mi][ni][2] + b0, l3 = acc[mi][ni][3] + b1;
            if (r < MTOT) {
                *reinterpret_cast<float2*>(out + (size_t)r * VV + c) =
                    make_float2(l0, l1);
                psum_lo[mi] += __expf(l0) + __expf(l1);
            }
            if (r + 8 < MTOT) {
                *reinterpret_cast<float2*>(out + (size_t)(r + 8) * VV + c) =
                    make_float2(l2, l3);
                psum_hi[mi] += __expf(l2) + __expf(l3);
            }
        }
    }
    __syncthreads();
    float* srow = (float*)smem;
    if (tid < BM) srow[tid] = 0.f;
    __syncthreads();
#pragma unroll
    for (int mi = 0; mi < 4; mi++) {
        atomicAdd(&srow[warpM * 64 + mi * 16 + g], psum_lo[mi]);
        atomicAdd(&srow[warpM * 64 + mi * 16 + 8 + g], psum_hi[mi]);
    }
    __syncthreads();
    if (tid < BM && m0 + tid < MTOT) atomicAdd(&g_rsum[m0 + tid], srow[tid]);
}

// ---------------------------------------------------------------------------
// Kernel 3: dense pass — in-place out[row, v] += log(pgen/rsum)
// ---------------------------------------------------------------------------
__global__ void dense_kernel(float* __restrict__ out) {
    int row = blockIdx.y;
    float C = __logf(g_pgen[row] / g_rsum[row]);
    float4* o4 = (float4*)(out + (size_t)row * VV);
    int j = blockIdx.x * 256 + threadIdx.x;
#pragma unroll
    for (int k = 0; k < 4; k++) {
        int i = j + k * 2048;
        if (i < V4) {
            float4 l = o4[i];
            l.x += C; l.y += C; l.z += C; l.w += C;
            o4[i] = l;
        }
    }
}

// ---------------------------------------------------------------------------
// Kernel 4: hash-merge copy distribution + apply at touched slots.
// ---------------------------------------------------------------------------
__global__ void hashapply_kernel(const float* __restrict__ attn,
                                 const int* __restrict__ enc,
                                 float* __restrict__ out) {
    int row = blockIdx.x;
    int b   = row / TT;
    const float* ar = attn + (size_t)row * LL;
    int tid = threadIdx.x;   // 256

    __shared__ float av[LL];
    __shared__ float red[256];
    __shared__ int   hidx[1024];
    __shared__ float hval[1024];

#pragma unroll
    for (int i = tid; i < 1024; i += 256) { hidx[i] = -1; hval[i] = 0.f; }

    float m = -1e30f;
    for (int l = tid; l < LL; l += 256) {
        float a = ar[l];
        av[l] = a;
        m = fmaxf(m, a);
    }
    red[tid] = m;
    __syncthreads();
    for (int off = 128; off > 0; off >>= 1) {
        if (tid < off) red[tid] = fmaxf(red[tid], red[tid + off]);
        __syncthreads();
    }
    m = red[0];
    __syncthreads();

    float s = 0.f;
    for (int l = tid; l < LL; l += 256) s += __expf(av[l] - m);
    red[tid] = s;
    __syncthreads();
    for (int off = 128; off > 0; off >>= 1) {
        if (tid < off) red[tid] += red[tid + off];
        __syncthreads();
    }
    s = red[0];

    float scale = (1.f - g_pgen[row]) / s;
    for (int l = tid; l < LL; l += 256) {
        float v = scale * __expf(av[l] - m);
        int id = enc[b * LL + l];
        int h = id & 1023;
        while (true) {
            int prev = atomicCAS(&hidx[h], -1, id);
            if (prev == -1 || prev == id) { atomicAdd(&hval[h], v); break; }
            h = (h + 1) & 1023;
        }
    }
    __syncthreads();

    for (int sslot = tid; sslot < 1024; sslot += 256) {
        int id = hidx[sslot];
        if (id >= 0) {
            size_t o = (size_t)row * VV + id;
            out[o] = __logf(hval[sslot] + __expf(out[o]));
        }
    }
}

// ---------------------------------------------------------------------------
extern "C" void kernel_launch(void* const* d_in, const int* in_sizes, int n_in,
                              void* d_out, int out_size) {
    const float* x    = (const float*)d_in[0];
    const float* attn = (const float*)d_in[1];
    const int*   enc  = (const int*)  d_in[2];
    const float* Wv   = (const float*)d_in[3];
    const float* bv   = (const float*)d_in[4];
    const float* wg   = (const float*)d_in[5];
    const float* bg   = (const float*)d_in[6];
    float* out = (float*)d_out;

    static bool attr_set = false;
    if (!attr_set) {
        cudaFuncSetAttribute(gemm_bf16, cudaFuncAttributeMaxDynamicSharedMemorySize,
                             SM_TOTAL);
        attr_set = true;
    }

    dim3 tgrid(VV / 64, HH / 64);
    transw_kernel<<<tgrid, 256>>>(Wv);
    pgen_kernel<<<MTOT, 256>>>(x, wg, bg);

    dim3 ggrid((MTOT + BM - 1) / BM, VV / BN);   // (7, 250), m fastest
    gemm_bf16<<<ggrid, GT, SM_TOTAL>>>(bv, out);

    dim3 dgrid(8, MTOT);
    dense_kernel<<<dgrid, 256>>>(out);

    hashapply_kernel<<<MTOT, 256>>>(attn, enc, out);
}